// round 9
// baseline (speedup 1.0000x reference)
#include <cuda_runtime.h>
#include <math.h>

// FeatureNormMagOnline — single-pass chained scan (decoupled lookback).
// EMA s_t = (1-a) s_{t-1} + a p_t  =>  over chunk of length L:
//   s_end = (1-a)^L * s_start + c_chunk
// One kernel: stage chunk in SMEM (single DRAM read), scan-from-zero ->
// publish partial + flag, spin on predecessors' flags, fold partials to get
// the exact start state, rescan from SMEM, write output (single DRAM write).
// Block IDs are ch-major: every block waits only on strictly lower IDs
// (CTAs dispatch in ID order -> deadlock-free, CUB decoupled-lookback style).

#define B_   16
#define C_   2
#define T_   1000
#define F_   257
#define BC_  (B_ * C_)     // 32
#define NCH  25
#define LCH  40            // NCH * LCH == T_
#define NTHR 288           // 9 warps; f = tid, guard f < 257

static const long long RES_ELEMS = (long long)B_ * C_ * T_ * F_ * 2;  // 16,448,000
static const int NSEQ = BC_ * F_;                                      // 8224
static const int SMEM_BYTES = LCH * F_ * 2 * 4;                        // 82,240 B

__device__ float g_part[NCH * BC_ * F_];   // partial EMA per (ch, bc, f)
__device__ int   g_flag[NCH * BC_];        // publish flags

__global__ void init_flags()
{
    int i = blockIdx.x * blockDim.x + threadIdx.x;
    if (i < NCH * BC_) g_flag[i] = 0;
}

__global__ void __launch_bounds__(NTHR, 2)
ema_scan_onepass(const float* __restrict__ in,
                 const float* __restrict__ weights,
                 const float* __restrict__ bias,
                 const float* __restrict__ alpha,
                 const float* __restrict__ s1,
                 float* __restrict__ out,
                 float* __restrict__ s_last_out)
{
    extern __shared__ float2 sx[];          // [LCH][F_]

    const int tid = threadIdx.x;
    const int bid = blockIdx.x;
    const int ch  = bid / BC_;              // ch-major: low ch = low block ID
    const int bc  = bid % BC_;
    const int c   = bc % C_;

    // ── stage chunk into SMEM (fully coalesced linear copy) ────────────────
    const float2* __restrict__ src =
        (const float2*)in + ((size_t)bc * T_ + (size_t)ch * LCH) * F_;
    #pragma unroll 4
    for (int i = tid; i < LCH * F_; i += NTHR)
        sx[i] = src[i];
    __syncthreads();

    const int  f     = tid;
    const bool valid = (f < F_);

    float a = 0.f, oma = 1.f, wgt = 0.f, bb = 0.f;
    if (valid) {
        a   = 1.0f / (1.0f + __expf(-alpha[c * F_ + f]));
        oma = 1.0f - a;
        wgt = weights[c * F_ + f];
        bb  = bias[c * F_ + f];
    }

    // ── phase 1: scan from zero, publish partial ───────────────────────────
    float s = 0.0f;
    if (valid) {
        #pragma unroll
        for (int tb = 0; tb < LCH; tb += 8) {
            float2 x[8];
            #pragma unroll
            for (int k = 0; k < 8; ++k) x[k] = sx[(tb + k) * F_ + f];
            #pragma unroll
            for (int k = 0; k < 8; ++k) {
                float p = fmaf(x[k].x, x[k].x, x[k].y * x[k].y);
                s = fmaf(oma, s, a * p);
            }
        }
        g_part[(ch * BC_ + bc) * F_ + f] = s;
    }
    __threadfence();
    __syncthreads();
    if (tid == 0) atomicExch(&g_flag[ch * BC_ + bc], 1);

    // ── lookback: wait for all predecessor chunks of this bc ───────────────
    if (tid < ch) {                          // <=24 lanes in warp 0 poll
        volatile int* fl = &g_flag[tid * BC_ + bc];
        while (*fl == 0) { }
    }
    __syncthreads();
    __threadfence();                         // acquire: partials now visible

    // ── fold partials -> exact chunk-start state ───────────────────────────
    float s0 = 0.0f;
    if (valid) {
        s0 = s1[bc * F_ + f];
        // oma^LCH (LCH=40) by repeated squaring: 6 multiplies
        float x2  = oma * oma;
        float x4  = x2 * x2;
        float x8  = x4 * x4;
        float x16 = x8 * x8;
        float x32 = x16 * x16;
        float omaL = x32 * x8;
        for (int i = 0; i < ch; ++i)
            s0 = fmaf(omaL, s0, g_part[(i * BC_ + bc) * F_ + f]);
    }

    // ── phase 2: rescan from SMEM with correct seed, write output ──────────
    if (valid) {
        float2* __restrict__ outp =
            (float2*)out + ((size_t)bc * T_ + (size_t)ch * LCH) * F_ + f;
        s = s0;
        #pragma unroll
        for (int tb = 0; tb < LCH; tb += 8) {
            float2 x[8];
            #pragma unroll
            for (int k = 0; k < 8; ++k) x[k] = sx[(tb + k) * F_ + f];
            float2 o[8];
            #pragma unroll
            for (int k = 0; k < 8; ++k) {
                float p = fmaf(x[k].x, x[k].x, x[k].y * x[k].y);
                s = fmaf(oma, s, a * p);
                float inv = __fdividef(wgt, sqrtf(s) + 1e-8f);
                o[k].x = fmaf(x[k].x, inv, bb);
                o[k].y = fmaf(x[k].y, inv, bb);
            }
            #pragma unroll
            for (int k = 0; k < 8; ++k)
                __stcs(outp + (size_t)(tb + k) * F_, o[k]);
        }
        if (ch == NCH - 1 && s_last_out)
            s_last_out[bc * F_ + f] = s;
    }
}

extern "C" void kernel_launch(void* const* d_in, const int* in_sizes, int n_in,
                              void* d_out, int out_size)
{
    const float* in      = (const float*)d_in[0];
    const float* weights = (const float*)d_in[1];
    const float* bias    = (const float*)d_in[2];
    const float* alpha   = (const float*)d_in[3];
    const float* s1      = (const float*)d_in[4];

    float* out = (float*)d_out;
    float* s_last = nullptr;
    if ((long long)out_size >= RES_ELEMS + NSEQ)
        s_last = out + RES_ELEMS;

    static bool attr_set = false;
    if (!attr_set) {
        cudaFuncSetAttribute(ema_scan_onepass,
                             cudaFuncAttributeMaxDynamicSharedMemorySize,
                             SMEM_BYTES);
        attr_set = true;
    }

    init_flags<<<(NCH * BC_ + 255) / 256, 256>>>();
    ema_scan_onepass<<<NCH * BC_, NTHR, SMEM_BYTES>>>(
        in, weights, bias, alpha, s1, out, s_last);
}

// round 10
// speedup vs baseline: 1.2258x; 1.2258x over previous
#include <cuda_runtime.h>
#include <math.h>

// FeatureNormMagOnline — single-pass chained scan, chunk held in REGISTERS.
// EMA s_t = (1-a) s_{t-1} + a p_t ; over chunk length L: s_end = (1-a)^L s0 + c.
// One kernel: each thread loads its chunk (40 float2) into registers with a
// fully unrolled batch (MLP~40), scans from zero, publishes partial + flag,
// waits on <=24 predecessor flags (all phase-1s run concurrently), folds the
// partials into the exact seed, rescans from registers, writes output.
// DRAM traffic = compulsory only: 66 MB read + 66 MB write.
// Block IDs ch-major: blocks wait only on strictly lower IDs (CUB-style
// decoupled lookback forward-progress argument).

#define B_   16
#define C_   2
#define T_   1000
#define F_   257
#define BC_  (B_ * C_)     // 32
#define NCH  25
#define LCH  40            // NCH * LCH == T_
#define NTHR 288           // f = tid, guard f < 257

static const long long RES_ELEMS = (long long)B_ * C_ * T_ * F_ * 2;  // 16,448,000
static const int NSEQ = BC_ * F_;                                      // 8224

__device__ float g_part[NCH * BC_ * F_];   // partial EMA per (ch, bc, f)
__device__ int   g_flag[NCH * BC_];        // publish flags

__global__ void init_flags()
{
    int i = blockIdx.x * blockDim.x + threadIdx.x;
    if (i < NCH * BC_) g_flag[i] = 0;
}

__global__ void __launch_bounds__(NTHR, 2)
ema_scan_regresident(const float* __restrict__ in,
                     const float* __restrict__ weights,
                     const float* __restrict__ bias,
                     const float* __restrict__ alpha,
                     const float* __restrict__ s1,
                     float* __restrict__ out,
                     float* __restrict__ s_last_out)
{
    const int tid = threadIdx.x;
    const int bid = blockIdx.x;
    const int ch  = bid / BC_;              // ch-major: low ch = low block ID
    const int bc  = bid % BC_;
    const int c   = bc % C_;

    const int  f     = tid;
    const bool valid = (f < F_);

    float a = 0.f, oma = 1.f, wgt = 0.f, bb = 0.f;
    if (valid) {
        a   = 1.0f / (1.0f + __expf(-alpha[c * F_ + f]));
        oma = 1.0f - a;
        wgt = weights[c * F_ + f];
        bb  = bias[c * F_ + f];
    }

    // ── load entire chunk into registers: 40 independent LDG.64 in flight ──
    const float2* __restrict__ inp =
        (const float2*)in + ((size_t)bc * T_ + (size_t)ch * LCH) * F_ + f;

    float2 x[LCH];
    if (valid) {
        #pragma unroll
        for (int t = 0; t < LCH; ++t)
            x[t] = __ldcs(inp + (size_t)t * F_);
    }

    // ── phase 1: scan from zero, publish partial ───────────────────────────
    float s = 0.0f;
    if (valid) {
        #pragma unroll
        for (int t = 0; t < LCH; ++t) {
            float p = fmaf(x[t].x, x[t].x, x[t].y * x[t].y);
            s = fmaf(oma, s, a * p);
        }
        g_part[(ch * BC_ + bc) * F_ + f] = s;
    }
    __threadfence();
    __syncthreads();
    if (tid == 0) atomicExch(&g_flag[ch * BC_ + bc], 1);

    // ── lookback: wait for all predecessor chunks of this bc ───────────────
    if (tid < ch) {                          // <=24 lanes of warp 0 poll
        volatile int* fl = &g_flag[tid * BC_ + bc];
        while (*fl == 0) { }
    }
    __syncthreads();
    __threadfence();                         // acquire: partials visible

    // ── fold partials -> exact chunk-start seed ────────────────────────────
    float s0 = 0.0f;
    if (valid) {
        s0 = s1[bc * F_ + f];
        float x2  = oma * oma;               // oma^40 via squaring
        float x4  = x2 * x2;
        float x8  = x4 * x4;
        float x16 = x8 * x8;
        float x32 = x16 * x16;
        float omaL = x32 * x8;
        for (int i = 0; i < ch; ++i)
            s0 = fmaf(omaL, s0, g_part[(i * BC_ + bc) * F_ + f]);
    }

    // ── phase 2: rescan from registers with correct seed, write output ─────
    if (valid) {
        float2* __restrict__ outp =
            (float2*)out + ((size_t)bc * T_ + (size_t)ch * LCH) * F_ + f;
        s = s0;
        #pragma unroll
        for (int t = 0; t < LCH; ++t) {
            float p = fmaf(x[t].x, x[t].x, x[t].y * x[t].y);
            s = fmaf(oma, s, a * p);
            float inv = __fdividef(wgt, sqrtf(s) + 1e-8f);
            float2 o;
            o.x = fmaf(x[t].x, inv, bb);
            o.y = fmaf(x[t].y, inv, bb);
            __stcs(outp + (size_t)t * F_, o);
        }
        if (ch == NCH - 1 && s_last_out)
            s_last_out[bc * F_ + f] = s;
    }
}

extern "C" void kernel_launch(void* const* d_in, const int* in_sizes, int n_in,
                              void* d_out, int out_size)
{
    const float* in      = (const float*)d_in[0];
    const float* weights = (const float*)d_in[1];
    const float* bias    = (const float*)d_in[2];
    const float* alpha   = (const float*)d_in[3];
    const float* s1      = (const float*)d_in[4];

    float* out = (float*)d_out;
    float* s_last = nullptr;
    if ((long long)out_size >= RES_ELEMS + NSEQ)
        s_last = out + RES_ELEMS;

    init_flags<<<(NCH * BC_ + 255) / 256, 256>>>();
    ema_scan_regresident<<<NCH * BC_, NTHR>>>(
        in, weights, bias, alpha, s1, out, s_last);
}

// round 12
// speedup vs baseline: 1.3325x; 1.0870x over previous
#include <cuda_runtime.h>
#include <math.h>

// FeatureNormMagOnline — 3-kernel fine-chunk scan decomposition.
// EMA s_t = (1-a) s_{t-1} + a p_t ; over chunk length L: s_end = (1-a)^L s0 + c.
//   pass1  : per (bc,ch,f) partial EMA from zero over LCH=10 steps (MLP=10/thread,
//            822K threads -> latency fully hidden). One compulsory 66MB DRAM read.
//   combine: per (bc,f) serial fold of 100 partials -> exclusive per-chunk seeds
//            + s_last. ~6.6MB of L2 traffic.
//   pass3  : per (bc,ch,f): seed + 10 L2-resident input loads + 10 output stores.
//            sqrt+div replaced by ONE rsqrt: inv = w*r*(1-1e-8*r), r=rsqrt(s);
//            rel err (1e-8*r)^2 — far below the 1e-3 tolerance.

#define B_   16
#define C_   2
#define T_   1000
#define F_   257
#define BC_  (B_ * C_)     // 32
#define NCH  100
#define LCH  10            // NCH * LCH == T_

static const long long RES_ELEMS = (long long)B_ * C_ * T_ * F_ * 2;  // 16,448,000
static const int NSEQ = BC_ * F_;            // 8224
static const int NIT  = BC_ * NCH * F_;      // 822,400 items for pass1/pass3

__device__ float g_part[NCH * BC_ * F_];     // partial EMA per (ch, bc, f)
__device__ float g_seed[NCH * BC_ * F_];     // exclusive chunk-start state

// ── pass 1: chunk partials from zero ─────────────────────────────────────────
__global__ void __launch_bounds__(256)
pass1_partials(const float* __restrict__ in,
               const float* __restrict__ alpha)
{
    int w = blockIdx.x * 256 + threadIdx.x;
    if (w >= NIT) return;
    int f  = w % F_;
    int q  = w / F_;
    int ch = q % NCH;
    int bc = q / NCH;
    int c  = bc % C_;

    float a   = 1.0f / (1.0f + __expf(-alpha[c * F_ + f]));
    float oma = 1.0f - a;

    const float2* __restrict__ inp =
        (const float2*)in + ((size_t)bc * T_ + (size_t)ch * LCH) * F_ + f;

    float2 x[LCH];
    #pragma unroll
    for (int t = 0; t < LCH; ++t)            // 10 independent LDG.64 in flight
        x[t] = inp[(size_t)t * F_];

    float s = 0.0f;
    #pragma unroll
    for (int t = 0; t < LCH; ++t) {
        float p = fmaf(x[t].x, x[t].x, x[t].y * x[t].y);
        s = fmaf(oma, s, a * p);
    }
    __stcs(&g_part[(ch * BC_ + bc) * F_ + f], s);   // streaming: read once
}

// ── pass 2: fold partials into exclusive seeds (+ s_last) ───────────────────
__global__ void __launch_bounds__(256)
combine_seeds(const float* __restrict__ alpha,
              const float* __restrict__ s1,
              float* __restrict__ s_last_out)
{
    int idx = blockIdx.x * 256 + threadIdx.x;
    if (idx >= NSEQ) return;
    int f  = idx % F_;
    int bc = idx / F_;
    int c  = bc % C_;

    float a   = 1.0f / (1.0f + __expf(-alpha[c * F_ + f]));
    float oma = 1.0f - a;
    // oma^10 by squaring: x8 * x2
    float x2 = oma * oma;
    float x4 = x2 * x2;
    float x8 = x4 * x4;
    float omaL = x8 * x2;

    float s = s1[idx];
    #pragma unroll
    for (int base = 0; base < NCH; base += 20) {
        float p[20];
        #pragma unroll
        for (int k = 0; k < 20; ++k)         // 20 independent L2 loads
            p[k] = g_part[((base + k) * BC_ + bc) * F_ + f];
        #pragma unroll
        for (int k = 0; k < 20; ++k) {
            g_seed[((base + k) * BC_ + bc) * F_ + f] = s;
            s = fmaf(omaL, s, p[k]);
        }
    }
    if (s_last_out) s_last_out[idx] = s;
}

// ── pass 3: rescan chunks with exact seeds, write normalized output ─────────
__global__ void __launch_bounds__(256)
pass3_output(const float* __restrict__ in,
             const float* __restrict__ weights,
             const float* __restrict__ bias,
             const float* __restrict__ alpha,
             float* __restrict__ out)
{
    int w = blockIdx.x * 256 + threadIdx.x;
    if (w >= NIT) return;
    int f  = w % F_;
    int q  = w / F_;
    int ch = q % NCH;
    int bc = q / NCH;
    int c  = bc % C_;
    int cf = c * F_ + f;

    float a   = 1.0f / (1.0f + __expf(-alpha[cf]));
    float oma = 1.0f - a;
    float wgt = weights[cf];
    float bb  = bias[cf];
    float s   = g_seed[(ch * BC_ + bc) * F_ + f];

    const float2* __restrict__ inp =
        (const float2*)in + ((size_t)bc * T_ + (size_t)ch * LCH) * F_ + f;
    float2* __restrict__ outp =
        (float2*)out      + ((size_t)bc * T_ + (size_t)ch * LCH) * F_ + f;

    float2 x[LCH];
    #pragma unroll
    for (int t = 0; t < LCH; ++t)            // last read of input: evict-first
        x[t] = __ldcs(inp + (size_t)t * F_);

    #pragma unroll
    for (int t = 0; t < LCH; ++t) {
        float p = fmaf(x[t].x, x[t].x, x[t].y * x[t].y);
        s = fmaf(oma, s, a * p);
        // inv = wgt / (sqrt(s) + 1e-8)  via one rsqrt:
        // r = 1/sqrt(s);  inv ~= wgt*r*(1 - 1e-8*r), rel err (1e-8*r)^2
        float r   = rsqrtf(fmaxf(s, 1e-24f));
        float inv = wgt * r * fmaf(-1e-8f, r, 1.0f);
        float2 o;
        o.x = fmaf(x[t].x, inv, bb);
        o.y = fmaf(x[t].y, inv, bb);
        __stcs(outp + (size_t)t * F_, o);
    }
}

extern "C" void kernel_launch(void* const* d_in, const int* in_sizes, int n_in,
                              void* d_out, int out_size)
{
    const float* in      = (const float*)d_in[0];
    const float* weights = (const float*)d_in[1];
    const float* bias    = (const float*)d_in[2];
    const float* alpha   = (const float*)d_in[3];
    const float* s1      = (const float*)d_in[4];

    float* out = (float*)d_out;
    float* s_last = nullptr;
    if ((long long)out_size >= RES_ELEMS + NSEQ)
        s_last = out + RES_ELEMS;

    int g13 = (NIT  + 255) / 256;   // 3213 blocks
    int g2  = (NSEQ + 255) / 256;   // 33 blocks

    pass1_partials<<<g13, 256>>>(in, alpha);
    combine_seeds <<<g2 , 256>>>(alpha, s1, s_last);
    pass3_output  <<<g13, 256>>>(in, weights, bias, alpha, out);
}

// round 14
// speedup vs baseline: 1.3896x; 1.0428x over previous
#include <cuda_runtime.h>
#include <math.h>

// FeatureNormMagOnline — 3-kernel fine-chunk scan decomposition, L2-resident.
// EMA s_t = (1-a) s_{t-1} + a p_t ; over chunk length L: s_end = (1-a)^L s0 + c.
//   pass1  : per (bc,ch,f) partial EMA from zero over LCH=10 steps (MLP=10).
//   combine: per (bc,f) fold of 100 partials -> exclusive per-chunk seeds + s_last.
//   pass3  : per (bc,ch,f): seed + 10 input loads + 10 output stores, 1 rsqrt.
// Steady-state (graph replay) cache policy: the 66MB input FITS in L2 (126MB)
// and persists across replays, so ALL input loads use default caching (ld.ca).
// Only the output write must touch DRAM; output stores are evict-first (stcs)
// so they don't evict the input. R12's __ldcs on pass3 input was the bug: it
// evicted the input every replay and forced pass1 to DRAM.

#define B_   16
#define C_   2
#define T_   1000
#define F_   257
#define BC_  (B_ * C_)     // 32
#define NCH  100
#define LCH  10            // NCH * LCH == T_

static const long long RES_ELEMS = (long long)B_ * C_ * T_ * F_ * 2;  // 16,448,000
static const int NSEQ = BC_ * F_;            // 8224
static const int NIT  = BC_ * NCH * F_;      // 822,400 items for pass1/pass3

__device__ float g_part[NCH * BC_ * F_];     // partial EMA per (ch, bc, f)
__device__ float g_seed[NCH * BC_ * F_];     // exclusive chunk-start state

// ── pass 1: chunk partials from zero ─────────────────────────────────────────
__global__ void __launch_bounds__(256)
pass1_partials(const float* __restrict__ in,
               const float* __restrict__ alpha)
{
    int w = blockIdx.x * 256 + threadIdx.x;
    if (w >= NIT) return;
    int f  = w % F_;
    int q  = w / F_;
    int ch = q % NCH;
    int bc = q / NCH;
    int c  = bc % C_;

    float a   = 1.0f / (1.0f + __expf(-alpha[c * F_ + f]));
    float oma = 1.0f - a;

    const float2* __restrict__ inp =
        (const float2*)in + ((size_t)bc * T_ + (size_t)ch * LCH) * F_ + f;

    float2 x[LCH];
    #pragma unroll
    for (int t = 0; t < LCH; ++t)            // 10 independent LDG.64 in flight
        x[t] = inp[(size_t)t * F_];          // default ld.ca: keep in L2

    float s = 0.0f;
    #pragma unroll
    for (int t = 0; t < LCH; ++t) {
        float p = fmaf(x[t].x, x[t].x, x[t].y * x[t].y);
        s = fmaf(oma, s, a * p);
    }
    g_part[(ch * BC_ + bc) * F_ + f] = s;
}

// ── pass 2: fold partials into exclusive seeds (+ s_last) ───────────────────
__global__ void __launch_bounds__(256)
combine_seeds(const float* __restrict__ alpha,
              const float* __restrict__ s1,
              float* __restrict__ s_last_out)
{
    int idx = blockIdx.x * 256 + threadIdx.x;
    if (idx >= NSEQ) return;
    int f  = idx % F_;
    int bc = idx / F_;
    int c  = bc % C_;

    float a   = 1.0f / (1.0f + __expf(-alpha[c * F_ + f]));
    float oma = 1.0f - a;
    // oma^10 by squaring: x8 * x2
    float x2 = oma * oma;
    float x4 = x2 * x2;
    float x8 = x4 * x4;
    float omaL = x8 * x2;

    float s = s1[idx];
    #pragma unroll
    for (int base = 0; base < NCH; base += 20) {
        float p[20];
        #pragma unroll
        for (int k = 0; k < 20; ++k)         // 20 independent L2 loads
            p[k] = g_part[((base + k) * BC_ + bc) * F_ + f];
        #pragma unroll
        for (int k = 0; k < 20; ++k) {
            g_seed[((base + k) * BC_ + bc) * F_ + f] = s;
            s = fmaf(omaL, s, p[k]);
        }
    }
    if (s_last_out) s_last_out[idx] = s;
}

// ── pass 3: rescan chunks with exact seeds, write normalized output ─────────
__global__ void __launch_bounds__(256)
pass3_output(const float* __restrict__ in,
             const float* __restrict__ weights,
             const float* __restrict__ bias,
             const float* __restrict__ alpha,
             float* __restrict__ out)
{
    int w = blockIdx.x * 256 + threadIdx.x;
    if (w >= NIT) return;
    int f  = w % F_;
    int q  = w / F_;
    int ch = q % NCH;
    int bc = q / NCH;
    int c  = bc % C_;
    int cf = c * F_ + f;

    float a   = 1.0f / (1.0f + __expf(-alpha[cf]));
    float oma = 1.0f - a;
    float wgt = weights[cf];
    float bb  = bias[cf];
    float s   = g_seed[(ch * BC_ + bc) * F_ + f];

    const float2* __restrict__ inp =
        (const float2*)in + ((size_t)bc * T_ + (size_t)ch * LCH) * F_ + f;
    float2* __restrict__ outp =
        (float2*)out      + ((size_t)bc * T_ + (size_t)ch * LCH) * F_ + f;

    float2 x[LCH];
    #pragma unroll
    for (int t = 0; t < LCH; ++t)
        x[t] = inp[(size_t)t * F_];          // default ld.ca: input STAYS in L2

    #pragma unroll
    for (int t = 0; t < LCH; ++t) {
        float p = fmaf(x[t].x, x[t].x, x[t].y * x[t].y);
        s = fmaf(oma, s, a * p);
        // inv = wgt / (sqrt(s) + 1e-8)  via one rsqrt:
        // r = 1/sqrt(s);  inv ~= wgt*r*(1 - 1e-8*r), rel err (1e-8*r)^2
        float r   = rsqrtf(fmaxf(s, 1e-24f));
        float inv = wgt * r * fmaf(-1e-8f, r, 1.0f);
        float2 o;
        o.x = fmaf(x[t].x, inv, bb);
        o.y = fmaf(x[t].y, inv, bb);
        __stcs(outp + (size_t)t * F_, o);    // evict-first: don't evict input
    }
}

extern "C" void kernel_launch(void* const* d_in, const int* in_sizes, int n_in,
                              void* d_out, int out_size)
{
    const float* in      = (const float*)d_in[0];
    const float* weights = (const float*)d_in[1];
    const float* bias    = (const float*)d_in[2];
    const float* alpha   = (const float*)d_in[3];
    const float* s1      = (const float*)d_in[4];

    float* out = (float*)d_out;
    float* s_last = nullptr;
    if ((long long)out_size >= RES_ELEMS + NSEQ)
        s_last = out + RES_ELEMS;

    int g13 = (NIT  + 255) / 256;   // 3213 blocks
    int g2  = (NSEQ + 255) / 256;   // 33 blocks

    pass1_partials<<<g13, 256>>>(in, alpha);
    combine_seeds <<<g2 , 256>>>(alpha, s1, s_last);
    pass3_output  <<<g13, 256>>>(in, weights, bias, alpha, out);
}